// round 2
// baseline (speedup 1.0000x reference)
#include <cuda_runtime.h>
#include <cuda_bf16.h>

// RNN: h_t = tanh(h_{t-1} + x_t @ W1 + b1), out = sigmoid(h_63 @ W2 + b2)
// x: [B, 64, 16] f32, W1: [16,10], b1: [10], W2: [10,5], b2: [5], out: [B,5] f32
//
// Mapping (round 2): hidden recurrence is elementwise per unit, so each thread
// owns ONE hidden unit for TWO batches, packed as f32x2 (lo=batch0, hi=batch1).
// W1 column dup-packed = 16 u64 = 32 regs (vs 160 before) -> 3 blocks/SM.
// Block = 320 threads = 32 batch-pairs x 10 units = 64 batches, no idle lanes.
// Producers (first 256 threads) stream x via LDG.128 (2-deep reg pipeline) and
// store pair-interleaved into smem so consumers do one broadcast LDS.64 per input.

#define SEQ   64
#define INF   16
#define HID   10
#define OUTF  5
#define ROWF  (SEQ*INF)     // 1024 floats per batch
#define PAIRS 32            // batch-pairs per block
#define PSTRIDE 17          // u64 stride per pair slot (conflict-free swizzle)
#define NTHREADS 320

typedef unsigned long long u64;

__device__ __forceinline__ u64 pack2(float lo, float hi) {
    u64 r; asm("mov.b64 %0, {%1,%2};" : "=l"(r) : "f"(lo), "f"(hi)); return r;
}
__device__ __forceinline__ void unpack2(float& lo, float& hi, u64 v) {
    asm("mov.b64 {%0,%1}, %2;" : "=f"(lo), "=f"(hi) : "l"(v));
}
__device__ __forceinline__ u64 fma2(u64 a, u64 b, u64 c) {
    u64 d; asm("fma.rn.f32x2 %0, %1, %2, %3;" : "=l"(d) : "l"(a), "l"(b), "l"(c)); return d;
}
__device__ __forceinline__ u64 add2(u64 a, u64 b) {
    u64 d; asm("add.rn.f32x2 %0, %1, %2;" : "=l"(d) : "l"(a), "l"(b)); return d;
}
// tanh(x) = 2/(1+exp(-2x)) - 1 ; ex2/rcp approx, ~1e-7 abs error
__device__ __forceinline__ float tanh_fast(float x) {
    float e; asm("ex2.approx.f32 %0, %1;" : "=f"(e) : "f"(x * -2.8853900817779268f));
    float r; asm("rcp.approx.f32 %0, %1;" : "=f"(r) : "f"(e + 1.0f));
    return fmaf(2.0f, r, -1.0f);
}
__device__ __forceinline__ float sigmoid_fast(float x) {
    float e; asm("ex2.approx.f32 %0, %1;" : "=f"(e) : "f"(x * -1.4426950408889634f));
    float r; asm("rcp.approx.f32 %0, %1;" : "=f"(r) : "f"(e + 1.0f));
    return r;
}

__global__ void __launch_bounds__(NTHREADS, 3)
rnn_kernel(const float* __restrict__ x,
           const float* __restrict__ W1,
           const float* __restrict__ b1,
           const float* __restrict__ W2,
           const float* __restrict__ b2,
           float* __restrict__ out,
           int nbatch)
{
    // two staging buffers, pair-interleaved: buf[st][p*PSTRIDE + i] = (x_{b0,i}, x_{b1,i})
    __shared__ u64 buf[2][PAIRS * PSTRIDE];

    const int t = threadIdx.x;
    const int u = t % HID;          // hidden unit 0..9
    const int p = t / HID;          // batch-pair 0..31
    const int blockBase = blockIdx.x * (2 * PAIRS);   // first batch of block

    // ---- per-thread weights: W1 column u, dup-packed ----
    u64 W1d[INF], b1d, h;
#pragma unroll
    for (int i = 0; i < INF; ++i) {
        float w = __ldg(W1 + i * HID + u);
        W1d[i] = pack2(w, w);
    }
    { float b = __ldg(b1 + u); b1d = pack2(b, b); }
    h = 0ull;

    // ---- producer role: first 256 threads, one float4 per step ----
    const int bl = t >> 2;          // batch-local 0..63 (t<256)
    const int w4 = t & 3;           // float4 index within a step
    const bool prod = (t < 256) && (blockBase + bl < nbatch);
    const float4* src = reinterpret_cast<const float4*>(
        x + (size_t)(blockBase + bl) * ROWF) + w4;     // + 4*s per step
    const int q  = bl & 1;
    const int pp = bl >> 1;
    // float index base into buf (as float array): 2*(pp*PSTRIDE + 4*w4) + q, +2 per k
    float* fbuf0 = reinterpret_cast<float*>(buf[0]) + 2 * (pp * PSTRIDE + 4 * w4) + q;
    float* fbuf1 = reinterpret_cast<float*>(buf[1]) + 2 * (pp * PSTRIDE + 4 * w4) + q;

    float4 v0, v1;
    if (prod) {
        v0 = __ldcs(src + 0);   // step 0
        v1 = __ldcs(src + 4);   // step 1
        fbuf0[0] = v0.x; fbuf0[2] = v0.y; fbuf0[4] = v0.z; fbuf0[6] = v0.w;  // STS(0)
    }
    __syncthreads();

    const u64* myrow0 = &buf[0][p * PSTRIDE];
    const u64* myrow1 = &buf[1][p * PSTRIDE];

#pragma unroll 2
    for (int s = 0; s < SEQ; ++s) {
        // feed pipeline: STS(s+1) from the alternating reg set, LDG(s+3... s+2)
        if (prod) {
            if (s + 1 < SEQ) {
                float* f = ((s + 1) & 1) ? fbuf1 : fbuf0;
                float4 vv = ((s + 1) & 1) ? v1 : v0;
                f[0] = vv.x; f[2] = vv.y; f[4] = vv.z; f[6] = vv.w;
            }
            if (s + 2 < SEQ) {
                float4 nv = __ldcs(src + 4 * (s + 2));
                if ((s & 1) == 0) v0 = nv; else v1 = nv;
            }
        }

        // compute step s (buf[s&1] filled by previous iteration's STS)
        const u64* row = (s & 1) ? myrow1 : myrow0;
        u64 a0 = add2(h, b1d);
        u64 a1 = fma2(row[1], W1d[1], 0ull);
        a0 = fma2(row[0], W1d[0], a0);
#pragma unroll
        for (int i = 2; i < INF; i += 2) {
            a0 = fma2(row[i],     W1d[i],     a0);
            a1 = fma2(row[i + 1], W1d[i + 1], a1);
        }
        u64 a = add2(a0, a1);
        float lo, hi; unpack2(lo, hi, a);
        h = pack2(tanh_fast(lo), tanh_fast(hi));

        __syncthreads();   // buf[(s+1)&1] now complete; buf[s&1] free for reuse
    }

    // ---- epilogue: gather h across units via smem, out = sigmoid(h @ W2 + b2) ----
    buf[0][p * PSTRIDE + u] = h;
    __syncthreads();

    if (u < OUTF) {
        const u64* hr = &buf[0][p * PSTRIDE];
        float bb = __ldg(b2 + u);
        u64 acc = pack2(bb, bb);
#pragma unroll
        for (int j = 0; j < HID; ++j) {
            float w = __ldg(W2 + j * OUTF + u);
            acc = fma2(hr[j], pack2(w, w), acc);
        }
        float lo, hi; unpack2(lo, hi, acc);
        lo = sigmoid_fast(lo);
        hi = sigmoid_fast(hi);
        long b0 = (long)blockBase + 2 * p;
        if (b0 < nbatch)     out[b0 * OUTF + u]       = lo;
        if (b0 + 1 < nbatch) out[(b0 + 1) * OUTF + u] = hi;
    }
}

extern "C" void kernel_launch(void* const* d_in, const int* in_sizes, int n_in,
                              void* d_out, int out_size)
{
    const float* x  = (const float*)d_in[0];
    const float* W1 = (const float*)d_in[1];
    const float* b1 = (const float*)d_in[2];
    const float* W2 = (const float*)d_in[3];
    const float* b2 = (const float*)d_in[4];
    float* out = (float*)d_out;

    int nbatch = in_sizes[0] / ROWF;                 // 65536
    int blocks = (nbatch + 2 * PAIRS - 1) / (2 * PAIRS);  // 1024
    rnn_kernel<<<blocks, NTHREADS>>>(x, W1, b1, W2, b2, out, nbatch);
}

// round 3
// speedup vs baseline: 1.7467x; 1.7467x over previous
#include <cuda_runtime.h>
#include <cuda_bf16.h>

// RNN: h_t = tanh(h_{t-1} + x_t @ W1 + b1), out = sigmoid(h_63 @ W2 + b2)
// x: [B, 64, 16] f32, W1: [16,10], b1: [10], W2: [10,5], b2: [5], out: [B,5] f32
//
// Round 3: warp-private (R1 structure) + 2-way hidden split to halve registers.
// Warp = 16 batches x 2 thread-halves. Each thread owns 5 hidden units of one
// batch (2 f32x2 unit-pairs + 1 scalar unit) -> 80 weight regs (vs 160).
// Producers = same warp: 2 LDG.128/thread/step staged into warp-private smem
// (row stride 20 floats, conflict-free LDS.128), __syncwarp only, no block sync.

#define SEQ   64
#define INF   16
#define HID   10
#define OUTF  5
#define ROWF  (SEQ*INF)     // 1024 floats per batch
#define RST   20            // smem row stride in floats (16B-aligned, conflict-free)
#define BPW   16            // batches per warp
#define WPB   4             // warps per block
#define SLOT  (BPW*RST)     // floats per slot

typedef unsigned long long u64;

__device__ __forceinline__ u64 pack2(float lo, float hi) {
    u64 r; asm("mov.b64 %0, {%1,%2};" : "=l"(r) : "f"(lo), "f"(hi)); return r;
}
__device__ __forceinline__ void unpack2(float& lo, float& hi, u64 v) {
    asm("mov.b64 {%0,%1}, %2;" : "=f"(lo), "=f"(hi) : "l"(v));
}
__device__ __forceinline__ u64 fma2(u64 a, u64 b, u64 c) {
    u64 d; asm("fma.rn.f32x2 %0, %1, %2, %3;" : "=l"(d) : "l"(a), "l"(b), "l"(c)); return d;
}
__device__ __forceinline__ u64 add2(u64 a, u64 b) {
    u64 d; asm("add.rn.f32x2 %0, %1, %2;" : "=l"(d) : "l"(a), "l"(b)); return d;
}
// tanh(x) = 2/(1+exp(-2x)) - 1 ; ex2/rcp approx, ~1e-7 abs error
__device__ __forceinline__ float tanh_fast(float x) {
    float e; asm("ex2.approx.f32 %0, %1;" : "=f"(e) : "f"(x * -2.8853900817779268f));
    float r; asm("rcp.approx.f32 %0, %1;" : "=f"(r) : "f"(e + 1.0f));
    return fmaf(2.0f, r, -1.0f);
}
__device__ __forceinline__ float sigmoid_fast(float x) {
    float e; asm("ex2.approx.f32 %0, %1;" : "=f"(e) : "f"(x * -1.4426950408889634f));
    float r; asm("rcp.approx.f32 %0, %1;" : "=f"(r) : "f"(e + 1.0f));
    return r;
}

__global__ void __launch_bounds__(128, 4)
rnn_kernel(const float* __restrict__ x,
           const float* __restrict__ W1,
           const float* __restrict__ b1,
           const float* __restrict__ W2,
           const float* __restrict__ b2,
           float* __restrict__ out,
           int nbatch)
{
    __shared__ float buf[WPB][2][SLOT];   // warp-private double buffer (10 KB)

    const int lane = threadIdx.x & 31;
    const int wid  = threadIdx.x >> 5;
    const int wbase = (blockIdx.x * WPB + wid) * BPW;
    if (wbase >= nbatch) return;

    const int half = lane & 1;        // which 5 units
    const int bl   = lane >> 1;       // batch-local 0..15
    const int ub   = half * 5;        // first unit

    // ---- per-thread weights: 5 units = 2 f32x2 pairs + 1 scalar ----
    u64 Wp0[INF], Wp1[INF]; float Ws[INF];
#pragma unroll
    for (int i = 0; i < INF; ++i) {
        Wp0[i] = pack2(__ldg(W1 + i*HID + ub),     __ldg(W1 + i*HID + ub + 1));
        Wp1[i] = pack2(__ldg(W1 + i*HID + ub + 2), __ldg(W1 + i*HID + ub + 3));
        Ws[i]  = __ldg(W1 + i*HID + ub + 4);
    }
    const u64 b1p0 = pack2(__ldg(b1 + ub),     __ldg(b1 + ub + 1));
    const u64 b1p1 = pack2(__ldg(b1 + ub + 2), __ldg(b1 + ub + 3));
    const float b1s = __ldg(b1 + ub + 4);
    u64 h0 = 0ull, h1 = 0ull; float hs = 0.0f;

    // ---- producer: each thread owns 2 float4 chunks per step ----
    const int g0 = lane, g1 = 32 + lane;
    const float4* src0 = reinterpret_cast<const float4*>(
        x + (size_t)(wbase + (g0 >> 2)) * ROWF) + (g0 & 3);
    const float4* src1 = reinterpret_cast<const float4*>(
        x + (size_t)(wbase + (g1 >> 2)) * ROWF) + (g1 & 3);
    float* sb = &buf[wid][0][0];
    float* st0 = sb + (g0 >> 2) * RST + (g0 & 3) * 4;   // chunk0 store addr (slot 0)
    float* st1 = sb + (g1 >> 2) * RST + (g1 & 3) * 4;

    float4 v0, v1;
    // step 0 -> slot 0
    v0 = __ldcs(src0);     v1 = __ldcs(src1);
    *reinterpret_cast<float4*>(st0) = v0;
    *reinterpret_cast<float4*>(st1) = v1;
    // step 1 held in regs
    v0 = __ldcs(src0 + 4); v1 = __ldcs(src1 + 4);
    __syncwarp();

    const float* myrow = sb + bl * RST;

    for (int s = 0; s < SEQ; ++s) {
        // feed pipeline first: STS(s+1), then LDG(s+2) (1-iteration lookahead)
        if (s + 1 < SEQ) {
            const int so = ((s + 1) & 1) * SLOT;
            *reinterpret_cast<float4*>(st0 + so) = v0;
            *reinterpret_cast<float4*>(st1 + so) = v1;
        }
        if (s + 2 < SEQ) {
            v0 = __ldcs(src0 + 4 * (s + 2));
            v1 = __ldcs(src1 + 4 * (s + 2));
        }

        // compute step s from slot s&1
        const float* row = myrow + (s & 1) * SLOT;
        const float4 q0 = *reinterpret_cast<const float4*>(row);
        const float4 q1 = *reinterpret_cast<const float4*>(row + 4);
        const float4 q2 = *reinterpret_cast<const float4*>(row + 8);
        const float4 q3 = *reinterpret_cast<const float4*>(row + 12);
        const float xs[INF] = {q0.x,q0.y,q0.z,q0.w, q1.x,q1.y,q1.z,q1.w,
                               q2.x,q2.y,q2.z,q2.w, q3.x,q3.y,q3.z,q3.w};
        u64 a0 = add2(h0, b1p0);
        u64 a1 = add2(h1, b1p1);
        float as = hs + b1s;
#pragma unroll
        for (int i = 0; i < INF; ++i) {
            const u64 xx = pack2(xs[i], xs[i]);
            a0 = fma2(xx, Wp0[i], a0);
            a1 = fma2(xx, Wp1[i], a1);
            as = fmaf(xs[i], Ws[i], as);
        }
        float l0, u0_, l1, u1_;
        unpack2(l0, u0_, a0);
        unpack2(l1, u1_, a1);
        h0 = pack2(tanh_fast(l0), tanh_fast(u0_));
        h1 = pack2(tanh_fast(l1), tanh_fast(u1_));
        hs = tanh_fast(as);

        __syncwarp();   // slot (s+1)&1 complete; slot s&1 free for overwrite
    }

    // ---- epilogue: each half has 5 units; partial h@W2, combine via shfl ----
    float hh[5];
    unpack2(hh[0], hh[1], h0);
    unpack2(hh[2], hh[3], h1);
    hh[4] = hs;

    float po[OUTF];
#pragma unroll
    for (int o = 0; o < OUTF; ++o) {
        float a = 0.0f;
#pragma unroll
        for (int k = 0; k < 5; ++k)
            a = fmaf(hh[k], __ldg(W2 + (ub + k) * OUTF + o), a);
        po[o] = a + __shfl_xor_sync(0xffffffffu, a, 1);
    }
    if (half == 0) {
        const long b = wbase + bl;
        if (b < nbatch) {
#pragma unroll
            for (int o = 0; o < OUTF; ++o)
                out[b * OUTF + o] = sigmoid_fast(po[o] + __ldg(b2 + o));
        }
    }
}

extern "C" void kernel_launch(void* const* d_in, const int* in_sizes, int n_in,
                              void* d_out, int out_size)
{
    const float* x  = (const float*)d_in[0];
    const float* W1 = (const float*)d_in[1];
    const float* b1 = (const float*)d_in[2];
    const float* W2 = (const float*)d_in[3];
    const float* b2 = (const float*)d_in[4];
    float* out = (float*)d_out;

    int nbatch = in_sizes[0] / ROWF;                       // 65536
    int blocks = (nbatch + WPB * BPW - 1) / (WPB * BPW);   // 1024
    rnn_kernel<<<blocks, WPB * 32>>>(x, W1, b1, W2, b2, out, nbatch);
}

// round 4
// speedup vs baseline: 2.4500x; 1.4026x over previous
#include <cuda_runtime.h>
#include <cuda_bf16.h>

// RNN: h_t = tanh(h_{t-1} + x_t @ W1 + b1), out = sigmoid(h_63 @ W2 + b2)
// x: [B, 64, 16] f32, W1: [16,10], b1: [10], W2: [10,5], b2: [5], out: [B,5] f32
//
// Round 4: R3 compute structure (warp = 16 batches x 2 unit-halves, FFMA2) +
// cp.async producer: 8-slot smem ring, 6-step lookahead, per-thread commit
// groups, __syncwarp-only synchronization. Accumulator chains split 2-way.

#define SEQ   64
#define INF   16
#define HID   10
#define OUTF  5
#define ROWF  (SEQ*INF)     // 1024 floats per batch
#define RST   20            // smem row stride in floats (16B aligned, conflict-free)
#define BPW   16            // batches per warp
#define WPB   4             // warps per block
#define SLOT  (BPW*RST)     // 320 floats per ring slot
#define NSLOT 8             // ring slots
#define LOOKA 6             // cp.async lookahead (groups in flight)

typedef unsigned long long u64;

__device__ __forceinline__ u64 pack2(float lo, float hi) {
    u64 r; asm("mov.b64 %0, {%1,%2};" : "=l"(r) : "f"(lo), "f"(hi)); return r;
}
__device__ __forceinline__ void unpack2(float& lo, float& hi, u64 v) {
    asm("mov.b64 {%0,%1}, %2;" : "=f"(lo), "=f"(hi) : "l"(v));
}
__device__ __forceinline__ u64 fma2(u64 a, u64 b, u64 c) {
    u64 d; asm("fma.rn.f32x2 %0, %1, %2, %3;" : "=l"(d) : "l"(a), "l"(b), "l"(c)); return d;
}
__device__ __forceinline__ u64 add2(u64 a, u64 b) {
    u64 d; asm("add.rn.f32x2 %0, %1, %2;" : "=l"(d) : "l"(a), "l"(b)); return d;
}
// tanh(x) = 2/(1+exp(-2x)) - 1 ; ex2/rcp approx, ~1e-7 abs error
__device__ __forceinline__ float tanh_fast(float x) {
    float e; asm("ex2.approx.f32 %0, %1;" : "=f"(e) : "f"(x * -2.8853900817779268f));
    float r; asm("rcp.approx.f32 %0, %1;" : "=f"(r) : "f"(e + 1.0f));
    return fmaf(2.0f, r, -1.0f);
}
__device__ __forceinline__ float sigmoid_fast(float x) {
    float e; asm("ex2.approx.f32 %0, %1;" : "=f"(e) : "f"(x * -1.4426950408889634f));
    float r; asm("rcp.approx.f32 %0, %1;" : "=f"(r) : "f"(e + 1.0f));
    return r;
}

#define CP16(dst, src) \
    asm volatile("cp.async.cg.shared.global [%0], [%1], 16;" :: "r"(dst), "l"(src))
#define CPCOMMIT() asm volatile("cp.async.commit_group;")
#define CPWAIT(n)  asm volatile("cp.async.wait_group %0;" :: "n"(n))

__global__ void __launch_bounds__(WPB * 32, 4)
rnn_kernel(const float* __restrict__ x,
           const float* __restrict__ W1,
           const float* __restrict__ b1,
           const float* __restrict__ W2,
           const float* __restrict__ b2,
           float* __restrict__ out,
           int nbatch)
{
    __shared__ float buf[WPB][NSLOT * SLOT];   // 4 x 10 KB warp-private rings

    const int lane = threadIdx.x & 31;
    const int wid  = threadIdx.x >> 5;
    const int wbase = (blockIdx.x * WPB + wid) * BPW;
    if (wbase >= nbatch) return;

    const int half = lane & 1;        // which 5 hidden units
    const int bl   = lane >> 1;       // batch-local 0..15
    const int ub   = half * 5;        // first unit of this half

    // ---- per-thread weights: 5 units = 2 f32x2 pairs + 1 scalar ----
    u64 Wp0[INF], Wp1[INF]; float Ws[INF];
#pragma unroll
    for (int i = 0; i < INF; ++i) {
        Wp0[i] = pack2(__ldg(W1 + i*HID + ub),     __ldg(W1 + i*HID + ub + 1));
        Wp1[i] = pack2(__ldg(W1 + i*HID + ub + 2), __ldg(W1 + i*HID + ub + 3));
        Ws[i]  = __ldg(W1 + i*HID + ub + 4);
    }
    const u64 b1p0 = pack2(__ldg(b1 + ub),     __ldg(b1 + ub + 1));
    const u64 b1p1 = pack2(__ldg(b1 + ub + 2), __ldg(b1 + ub + 3));
    const float b1s = __ldg(b1 + ub + 4);
    u64 h0 = 0ull, h1 = 0ull; float hs = 0.0f;

    // ---- producer addressing: 2 x 16B chunks per thread per step ----
    const int g0 = lane, g1 = 32 + lane;
    const float4* src0 = reinterpret_cast<const float4*>(
        x + (size_t)(wbase + (g0 >> 2)) * ROWF) + (g0 & 3);
    const float4* src1 = reinterpret_cast<const float4*>(
        x + (size_t)(wbase + (g1 >> 2)) * ROWF) + (g1 & 3);

    float* sbf = &buf[wid][0];
    const unsigned sb32 = (unsigned)__cvta_generic_to_shared(sbf);
    const unsigned st0 = sb32 + (((g0 >> 2) * RST + (g0 & 3) * 4) << 2);
    const unsigned st1 = sb32 + (((g1 >> 2) * RST + (g1 & 3) * 4) << 2);

    // prologue: launch LOOKA steps, one commit group each
#pragma unroll
    for (int k = 0; k < LOOKA; ++k) {
        const unsigned so = (unsigned)(k & (NSLOT - 1)) * (SLOT * 4);
        CP16(st0 + so, src0 + 4 * k);
        CP16(st1 + so, src1 + 4 * k);
        CPCOMMIT();
    }

    const float* myrow = sbf + bl * RST;

    for (int s = 0; s < SEQ; ++s) {
        CPWAIT(LOOKA - 1);    // group for step s complete (this thread)
        __syncwarp();         // cross-lane visibility of slot s

        // keep the pipeline full: step s+LOOKA into slot (s+LOOKA)%NSLOT
        {
            const int f = s + LOOKA;
            if (f < SEQ) {
                const unsigned so = (unsigned)(f & (NSLOT - 1)) * (SLOT * 4);
                CP16(st0 + so, src0 + 4 * f);
                CP16(st1 + so, src1 + 4 * f);
            }
            CPCOMMIT();       // empty group in the tail keeps wait-count exact
        }

        // compute step s from slot s%NSLOT
        const float* row = myrow + (s & (NSLOT - 1)) * SLOT;
        const float4 q0 = *reinterpret_cast<const float4*>(row);
        const float4 q1 = *reinterpret_cast<const float4*>(row + 4);
        const float4 q2 = *reinterpret_cast<const float4*>(row + 8);
        const float4 q3 = *reinterpret_cast<const float4*>(row + 12);
        const float xs[INF] = {q0.x,q0.y,q0.z,q0.w, q1.x,q1.y,q1.z,q1.w,
                               q2.x,q2.y,q2.z,q2.w, q3.x,q3.y,q3.z,q3.w};

        // 6 accumulator chains (8-deep each) for ILP
        u64 a0a = add2(h0, b1p0), a0b = 0ull;
        u64 a1a = add2(h1, b1p1), a1b = 0ull;
        float asa = hs + b1s, asb = 0.0f;
#pragma unroll
        for (int i = 0; i < INF; i += 2) {
            const u64 xA = pack2(xs[i], xs[i]);
            const u64 xB = pack2(xs[i+1], xs[i+1]);
            a0a = fma2(xA, Wp0[i],   a0a);
            a1a = fma2(xA, Wp1[i],   a1a);
            asa = fmaf(xs[i],   Ws[i],   asa);
            a0b = fma2(xB, Wp0[i+1], a0b);
            a1b = fma2(xB, Wp1[i+1], a1b);
            asb = fmaf(xs[i+1], Ws[i+1], asb);
        }
        const u64 a0 = add2(a0a, a0b);
        const u64 a1 = add2(a1a, a1b);
        const float as = asa + asb;

        float l0, u0_, l1, u1_;
        unpack2(l0, u0_, a0);
        unpack2(l1, u1_, a1);
        h0 = pack2(tanh_fast(l0), tanh_fast(u0_));
        h1 = pack2(tanh_fast(l1), tanh_fast(u1_));
        hs = tanh_fast(as);
    }

    // ---- epilogue: partial h@W2 per half, combine via shfl ----
    float hh[5];
    unpack2(hh[0], hh[1], h0);
    unpack2(hh[2], hh[3], h1);
    hh[4] = hs;

    float po[OUTF];
#pragma unroll
    for (int o = 0; o < OUTF; ++o) {
        float a = 0.0f;
#pragma unroll
        for (int k = 0; k < 5; ++k)
            a = fmaf(hh[k], __ldg(W2 + (ub + k) * OUTF + o), a);
        po[o] = a + __shfl_xor_sync(0xffffffffu, a, 1);
    }
    if (half == 0) {
        const long b = wbase + bl;
        if (b < nbatch) {
#pragma unroll
            for (int o = 0; o < OUTF; ++o)
                out[b * OUTF + o] = sigmoid_fast(po[o] + __ldg(b2 + o));
        }
    }
}

extern "C" void kernel_launch(void* const* d_in, const int* in_sizes, int n_in,
                              void* d_out, int out_size)
{
    const float* x  = (const float*)d_in[0];
    const float* W1 = (const float*)d_in[1];
    const float* b1 = (const float*)d_in[2];
    const float* W2 = (const float*)d_in[3];
    const float* b2 = (const float*)d_in[4];
    float* out = (float*)d_out;

    int nbatch = in_sizes[0] / ROWF;                       // 65536
    int blocks = (nbatch + WPB * BPW - 1) / (WPB * BPW);   // 1024
    rnn_kernel<<<blocks, WPB * 32>>>(x, W1, b1, W2, b2, out, nbatch);
}

// round 5
// speedup vs baseline: 2.7342x; 1.1160x over previous
#include <cuda_runtime.h>
#include <cuda_bf16.h>

// RNN: h_t = tanh(h_{t-1} + x_t @ W1 + b1), out = sigmoid(h_63 @ W2 + b2)
// x: [B, 64, 16] f32, W1: [16,10], b1: [10], W2: [10,5], b2: [5], out: [B,5] f32
//
// Round 5: K-pair FFMA2 packing. Accumulator f32x2 lanes = partial sums over
// even/odd inputs of the SAME hidden unit, so the x-pair (x_2i, x_2i+1) comes
// directly from LDS.128 (no dup movs, no scalar fmaf tail): 40 fma2 = all 80
// FMA per step. tanh via single MUFU.TANH. cp.async 8-slot ring (R4) kept.

#define SEQ   64
#define INF   16
#define HID   10
#define OUTF  5
#define ROWF  (SEQ*INF)     // 1024 floats per batch
#define RST   20            // smem row stride in floats (16B aligned)
#define BPW   16            // batches per warp
#define WPB   4             // warps per block
#define SLOT  (BPW*RST)     // 320 floats per ring slot
#define NSLOT 8             // ring slots
#define LOOKA 6             // cp.async lookahead

typedef unsigned long long u64;

__device__ __forceinline__ u64 pack2(float lo, float hi) {
    u64 r; asm("mov.b64 %0, {%1,%2};" : "=l"(r) : "f"(lo), "f"(hi)); return r;
}
__device__ __forceinline__ void unpack2(float& lo, float& hi, u64 v) {
    asm("mov.b64 {%0,%1}, %2;" : "=f"(lo), "=f"(hi) : "l"(v));
}
__device__ __forceinline__ u64 fma2(u64 a, u64 b, u64 c) {
    u64 d; asm("fma.rn.f32x2 %0, %1, %2, %3;" : "=l"(d) : "l"(a), "l"(b), "l"(c)); return d;
}
__device__ __forceinline__ float tanh_fast(float x) {
    float y; asm("tanh.approx.f32 %0, %1;" : "=f"(y) : "f"(x)); return y;
}
__device__ __forceinline__ float sigmoid_fast(float x) {
    float e; asm("ex2.approx.f32 %0, %1;" : "=f"(e) : "f"(x * -1.4426950408889634f));
    float r; asm("rcp.approx.f32 %0, %1;" : "=f"(r) : "f"(e + 1.0f));
    return r;
}

#define CP16(dst, src) \
    asm volatile("cp.async.cg.shared.global [%0], [%1], 16;" :: "r"(dst), "l"(src))
#define CPCOMMIT() asm volatile("cp.async.commit_group;")
#define CPWAIT(n)  asm volatile("cp.async.wait_group %0;" :: "n"(n))

__global__ void __launch_bounds__(WPB * 32, 4)
rnn_kernel(const float* __restrict__ x,
           const float* __restrict__ W1,
           const float* __restrict__ b1,
           const float* __restrict__ W2,
           const float* __restrict__ b2,
           float* __restrict__ out,
           int nbatch)
{
    __shared__ float buf[WPB][NSLOT * SLOT];   // 4 x 10 KB warp-private rings

    const int lane = threadIdx.x & 31;
    const int wid  = threadIdx.x >> 5;
    const int wbase = (blockIdx.x * WPB + wid) * BPW;
    if (wbase >= nbatch) return;

    const int half = lane & 1;        // which 5 hidden units
    const int bl   = lane >> 1;       // batch-local 0..15
    const int ub   = half * 5;        // first unit of this half

    // ---- per-thread weights, K-pair packed: Wq[ip][j] = (W1[2ip][ub+j], W1[2ip+1][ub+j])
    u64 Wq[8][5];
#pragma unroll
    for (int ip = 0; ip < 8; ++ip)
#pragma unroll
        for (int j = 0; j < 5; ++j)
            Wq[ip][j] = pack2(__ldg(W1 + (2*ip)*HID + ub + j),
                              __ldg(W1 + (2*ip+1)*HID + ub + j));
    float b1v[5], h[5], hb[5];
#pragma unroll
    for (int j = 0; j < 5; ++j) { b1v[j] = __ldg(b1 + ub + j); h[j] = 0.0f; hb[j] = b1v[j]; }

    // ---- producer addressing: 2 x 16B chunks per thread per step ----
    // chunk0: batch bl0=lane>>2 (0..7), word w=lane&3; chunk1 = +8 batches (const offsets)
    const float4* src0 = reinterpret_cast<const float4*>(
        x + (size_t)(wbase + (lane >> 2)) * ROWF) + (lane & 3);
    float* sbf = &buf[wid][0];
    const unsigned sb32 = (unsigned)__cvta_generic_to_shared(sbf);
    const unsigned st0 = sb32 + ((((lane >> 2)) * RST + (lane & 3) * 4) << 2);
    const unsigned D_ST = 8 * RST * 4;          // +8 batches in smem (bytes)
    const size_t   D_SRC = (size_t)8 * ROWF;    // +8 batches in gmem (float4s = *4 floats)

    // prologue: LOOKA steps in flight, one commit group each
#pragma unroll
    for (int k = 0; k < LOOKA; ++k) {
        const unsigned so = (unsigned)(k & (NSLOT - 1)) * (SLOT * 4);
        CP16(st0 + so,        src0 + 4 * k);
        CP16(st0 + so + D_ST, src0 + 4 * k + 2 * ROWF);   // 8*ROWF floats = 2*ROWF float4
        CPCOMMIT();
    }

    const float* myrow = sbf + bl * RST;

#pragma unroll 2
    for (int s = 0; s < SEQ; ++s) {
        CPWAIT(LOOKA - 1);    // group for step s complete (this thread)
        __syncwarp();         // cross-lane visibility of slot s

        // keep pipeline full: step s+LOOKA
        {
            const int f = s + LOOKA;
            if (f < SEQ) {
                const unsigned so = (unsigned)(f & (NSLOT - 1)) * (SLOT * 4);
                CP16(st0 + so,        src0 + 4 * f);
                CP16(st0 + so + D_ST, src0 + 4 * f + 2 * ROWF);
            }
            CPCOMMIT();       // empty tail group keeps wait-count exact
        }

        // compute step s: x-pairs straight from LDS.128
        const ulonglong2* rowq =
            reinterpret_cast<const ulonglong2*>(myrow + (s & (NSLOT - 1)) * SLOT);
        u64 a0 = 0, a1 = 0, a2 = 0, a3 = 0, a4 = 0;

        {   // inputs 0..7 (2 LDS.128)
            const ulonglong2 p0 = rowq[0];
            const ulonglong2 p1 = rowq[1];
            const u64 xq[4] = {p0.x, p0.y, p1.x, p1.y};
#pragma unroll
            for (int ip = 0; ip < 4; ++ip) {
                a0 = fma2(xq[ip], Wq[ip][0], a0);
                a1 = fma2(xq[ip], Wq[ip][1], a1);
                a2 = fma2(xq[ip], Wq[ip][2], a2);
                a3 = fma2(xq[ip], Wq[ip][3], a3);
                a4 = fma2(xq[ip], Wq[ip][4], a4);
            }
        }
        {   // inputs 8..15 (2 LDS.128)
            const ulonglong2 p2 = rowq[2];
            const ulonglong2 p3 = rowq[3];
            const u64 xq[4] = {p2.x, p2.y, p3.x, p3.y};
#pragma unroll
            for (int ip = 0; ip < 4; ++ip) {
                a0 = fma2(xq[ip], Wq[4 + ip][0], a0);
                a1 = fma2(xq[ip], Wq[4 + ip][1], a1);
                a2 = fma2(xq[ip], Wq[4 + ip][2], a2);
                a3 = fma2(xq[ip], Wq[4 + ip][3], a3);
                a4 = fma2(xq[ip], Wq[4 + ip][4], a4);
            }
        }

        // h_j = tanh(hb_j + lo_j + hi_j);  hb_j = h_j + b1_j (feeds next step)
        u64 aa[5] = {a0, a1, a2, a3, a4};
#pragma unroll
        for (int j = 0; j < 5; ++j) {
            float lo, hi; unpack2(lo, hi, aa[j]);
            h[j]  = tanh_fast(hb[j] + (lo + hi));
            hb[j] = h[j] + b1v[j];
        }
    }

    // ---- epilogue: partial h@W2 per half, combine via shfl ----
    float po[OUTF];
#pragma unroll
    for (int o = 0; o < OUTF; ++o) {
        float a = 0.0f;
#pragma unroll
        for (int k = 0; k < 5; ++k)
            a = fmaf(h[k], __ldg(W2 + (ub + k) * OUTF + o), a);
        po[o] = a + __shfl_xor_sync(0xffffffffu, a, 1);
    }
    if (half == 0) {
        const long b = wbase + bl;
        if (b < nbatch) {
#pragma unroll
            for (int o = 0; o < OUTF; ++o)
                out[b * OUTF + o] = sigmoid_fast(po[o] + __ldg(b2 + o));
        }
    }
}

extern "C" void kernel_launch(void* const* d_in, const int* in_sizes, int n_in,
                              void* d_out, int out_size)
{
    const float* x  = (const float*)d_in[0];
    const float* W1 = (const float*)d_in[1];
    const float* b1 = (const float*)d_in[2];
    const float* W2 = (const float*)d_in[3];
    const float* b2 = (const float*)d_in[4];
    float* out = (float*)d_out;

    int nbatch = in_sizes[0] / ROWF;                       // 65536
    int blocks = (nbatch + WPB * BPW - 1) / (WPB * BPW);   // 1024
    rnn_kernel<<<blocks, WPB * 32>>>(x, W1, b1, W2, b2, out, nbatch);
}